// round 10
// baseline (speedup 1.0000x reference)
#include <cuda_runtime.h>
#include <math.h>

// ---------------------------------------------------------------------------
// AttentiveKnrmLayer  (B=64, NB=8, Q=32, T=256, D=256, N_BINS=11)
//
// Inputs (metadata order):
//  0 word_atten   [B,NB,Q]        f32
//  1 hq           [B,NB,Q,D]      f32
//  2 can          [B,T,D]         f32
//  3 rep          [B,NB,D]        f32
//  4 rep_cur      [B,D]           f32
//  5 mask_hq      [B,NB,Q]        f32
//  6 mask_can     [B,T]           f32
//  7 mask_session [B,NB]          f32
//  8 W_dense      [11,1]          f32
//  9 b_dense      [1]             f32
// 10 W_att        [D,D]           f32
// 11 b_att        [D]             f32
// output: [B] f32
// ---------------------------------------------------------------------------

#define B_    64
#define NB_   8
#define Q_    32
#define T_    256
#define D_    256
#define NBIN  11

// scratch (no cudaMalloc allowed)
__device__ float g_hq_n[B_ * NB_ * Q_ * D_];   // 16.8 MB
__device__ float g_can_n[B_ * T_ * D_];        // 4.2 MB
__device__ float g_score[B_ * NB_];            // tanh(pooled @ W_dense + b)

// Gaussian bin constants: kern = exp(-(m-mu)^2 / (2 sigma^2))
//                             = exp2( (m-mu)^2 * C2 ),  C2 = -log2(e)/(2 sigma^2)
__constant__ float c_mu[NBIN] = {1.0f, 0.9f, 0.7f, 0.5f, 0.3f, 0.1f,
                                 -0.1f, -0.3f, -0.5f, -0.7f, -0.9f};
__constant__ float c_c2[NBIN] = {
    -721347.52f,                      // sigma = 1e-3
    -72.13475204f, -72.13475204f, -72.13475204f, -72.13475204f, -72.13475204f,
    -72.13475204f, -72.13475204f, -72.13475204f, -72.13475204f, -72.13475204f};

// ---------------------------------------------------------------------------
// Kernel 1: L2-normalize hq and can rows (one warp per 256-float row).
// rows [0, 16384)  -> hq rows, rows [16384, 32768) -> can rows
// ---------------------------------------------------------------------------
__global__ __launch_bounds__(256) void normalize_kernel(
    const float* __restrict__ hq, const float* __restrict__ can)
{
    const int warp = threadIdx.x >> 5;
    const int lane = threadIdx.x & 31;
    const int row  = blockIdx.x * 8 + warp;

    const float* src;
    float* dst;
    if (row < B_ * NB_ * Q_) {
        src = hq + (size_t)row * D_;
        dst = g_hq_n + (size_t)row * D_;
    } else {
        int r = row - B_ * NB_ * Q_;
        src = can + (size_t)r * D_;
        dst = g_can_n + (size_t)r * D_;
    }

    float v[8];
    float ss = 0.f;
#pragma unroll
    for (int r = 0; r < 8; r++) {
        v[r] = src[lane + 32 * r];
        ss += v[r] * v[r];
    }
#pragma unroll
    for (int off = 16; off > 0; off >>= 1)
        ss += __shfl_xor_sync(0xffffffffu, ss, off);

    // F.normalize semantics: x / max(||x||, eps)
    float inv = 1.0f / fmaxf(sqrtf(ss), 1e-10f);
#pragma unroll
    for (int r = 0; r < 8; r++)
        dst[lane + 32 * r] = v[r] * inv;
}

// ---------------------------------------------------------------------------
// Kernel 2: per (b, n): fp32 GEMM (32x256 @ 256x256^T) fused with Gaussian
// soft-binning, log-pool over T, weighted sum over Q, dense + tanh.
// Grid: (NB, B). Block: 256 threads = 8 warps.
// Warp w owns q in [4w, 4w+4); lane tt owns t in {j*32 + tt : j<8}.
// ---------------------------------------------------------------------------
__global__ __launch_bounds__(256) void knrm_kernel(
    const float* __restrict__ word_atten,
    const float* __restrict__ mask_hq,
    const float* __restrict__ mask_can,
    const float* __restrict__ mask_session,
    const float* __restrict__ W_dense,
    const float* __restrict__ b_dense)
{
    const int n = blockIdx.x;     // session block
    const int b = blockIdx.y;     // batch
    const int bn = b * NB_ + n;

    const float* hq = g_hq_n + (size_t)bn * Q_ * D_;
    const float* cn = g_can_n + (size_t)b * T_ * D_;

    __shared__ float hq_s[Q_][36];     // K-chunk of hq, pad 36
    __shared__ float cs[T_][36];       // K-chunk of can, pad 36
    __shared__ float lp_s[Q_][12];     // per-q log-pooled bins
    __shared__ float pooled_s[NBIN];

    const int tid = threadIdx.x;
    const int tt  = tid & 31;          // lane -> t group
    const int qt  = tid >> 5;          // warp -> q group
    const int q0  = qt * 4;

    float acc[4][8];
#pragma unroll
    for (int i = 0; i < 4; i++)
#pragma unroll
        for (int j = 0; j < 8; j++) acc[i][j] = 0.f;

    // doc-token masks for this lane's 8 t's
    float mc[8];
#pragma unroll
    for (int j = 0; j < 8; j++)
        mc[j] = mask_can[b * T_ + j * 32 + tt];

    // ---- GEMM: K chunked by 32 --------------------------------------------
    for (int k0 = 0; k0 < D_; k0 += 32) {
        __syncthreads();   // previous chunk fully consumed

        // load cs chunk: 256 rows x 32 floats (8 float4 per row)
        {
            const int c = tid & 7;          // float4 column within chunk
            const int tr = tid >> 3;        // 0..31
#pragma unroll
            for (int p = 0; p < 8; p++) {
                int t = p * 32 + tr;
                float4 v = *(const float4*)&cn[(size_t)t * D_ + k0 + c * 4];
                *(float4*)&cs[t][c * 4] = v;
            }
            // load hq chunk: 32 rows x 32 floats (256 float4 -> 1 per thread)
            int qrow = tid >> 3;
            float4 h = *(const float4*)&hq[(size_t)qrow * D_ + k0 + c * 4];
            *(float4*)&hq_s[qrow][c * 4] = h;
        }
        __syncthreads();

#pragma unroll
        for (int kk = 0; kk < 32; kk += 4) {
            float4 a0 = *(const float4*)&hq_s[q0 + 0][kk];
            float4 a1 = *(const float4*)&hq_s[q0 + 1][kk];
            float4 a2 = *(const float4*)&hq_s[q0 + 2][kk];
            float4 a3 = *(const float4*)&hq_s[q0 + 3][kk];
#pragma unroll
            for (int j = 0; j < 8; j++) {
                float4 cv = *(const float4*)&cs[j * 32 + tt][kk];
                acc[0][j] = fmaf(a0.x, cv.x, fmaf(a0.y, cv.y, fmaf(a0.z, cv.z, fmaf(a0.w, cv.w, acc[0][j]))));
                acc[1][j] = fmaf(a1.x, cv.x, fmaf(a1.y, cv.y, fmaf(a1.z, cv.z, fmaf(a1.w, cv.w, acc[1][j]))));
                acc[2][j] = fmaf(a2.x, cv.x, fmaf(a2.y, cv.y, fmaf(a2.z, cv.z, fmaf(a2.w, cv.w, acc[2][j]))));
                acc[3][j] = fmaf(a3.x, cv.x, fmaf(a3.y, cv.y, fmaf(a3.z, cv.z, fmaf(a3.w, cv.w, acc[3][j]))));
            }
        }
    }

    // ---- Gaussian soft-binning + pooling over T ---------------------------
#pragma unroll
    for (int i = 0; i < 4; i++) {
        float bins[NBIN];
#pragma unroll
        for (int bb = 0; bb < NBIN; bb++) bins[bb] = 0.f;

#pragma unroll
        for (int j = 0; j < 8; j++) {
            float m = acc[i][j];
            float w = mc[j];
#pragma unroll
            for (int bb = 0; bb < NBIN; bb++) {
                float d = m - c_mu[bb];
                bins[bb] += w * exp2f(d * d * c_c2[bb]);
            }
        }
        // warp reduce (covers all 256 t)
#pragma unroll
        for (int bb = 0; bb < NBIN; bb++) {
            float s = bins[bb];
#pragma unroll
            for (int off = 16; off > 0; off >>= 1)
                s += __shfl_xor_sync(0xffffffffu, s, off);
            bins[bb] = s;
        }
        if (tt == 0) {
            int q = q0 + i;
            float w = mask_hq[bn * Q_ + q] * word_atten[bn * Q_ + q];
#pragma unroll
            for (int bb = 0; bb < NBIN; bb++)
                lp_s[q][bb] = logf(fmaxf(bins[bb], 1e-10f)) * 0.01f * w;
        }
    }
    __syncthreads();

    // ---- sum over Q (fixed order, deterministic), mask_session ------------
    if (tid < NBIN) {
        float s = 0.f;
#pragma unroll
        for (int q = 0; q < Q_; q++) s += lp_s[q][tid];
        pooled_s[tid] = s * mask_session[bn];
    }
    __syncthreads();

    // ---- dense + tanh -------------------------------------------------------
    if (tid == 0) {
        float z = b_dense[0];
#pragma unroll
        for (int bb = 0; bb < NBIN; bb++) z += pooled_s[bb] * W_dense[bb];
        g_score[bn] = tanhf(z);
    }
}

// ---------------------------------------------------------------------------
// Kernel 3: session attention + final combine.  One block per batch b.
// ---------------------------------------------------------------------------
__global__ __launch_bounds__(256) void attend_kernel(
    const float* __restrict__ rep,
    const float* __restrict__ rep_cur,
    const float* __restrict__ mask_session,
    const float* __restrict__ W_att,
    const float* __restrict__ b_att,
    float* __restrict__ out)
{
    const int b = blockIdx.x;
    const int tid = threadIdx.x;

    __shared__ float rc[D_];
    __shared__ float qv[D_];
    __shared__ float sc[NB_];

    rc[tid] = rep_cur[b * D_ + tid];
    __syncthreads();

    // q = rep_cur @ W_att + b_att  (thread tid -> output dim tid)
    float s = b_att[tid];
    for (int i = 0; i < D_; i++)
        s = fmaf(rc[i], W_att[(size_t)i * D_ + tid], s);
    qv[tid] = s;
    __syncthreads();

    // scores[n] = dot(rep[b,n], q) / 16   (warp w -> n = w)
    const int w = tid >> 5, lane = tid & 31;
    float p = 0.f;
#pragma unroll
    for (int r = 0; r < 8; r++) {
        int d = lane + 32 * r;
        p = fmaf(rep[((size_t)b * NB_ + w) * D_ + d], qv[d], p);
    }
#pragma unroll
    for (int off = 16; off > 0; off >>= 1)
        p += __shfl_xor_sync(0xffffffffu, p, off);
    if (lane == 0) sc[w] = p * (1.0f / 16.0f);
    __syncthreads();

    if (tid == 0) {
        float sv[NB_];
        float mx = -1e30f;
#pragma unroll
        for (int n = 0; n < NB_; n++) {
            float v = (mask_session[b * NB_ + n] > 0.f) ? sc[n] : -1e9f;
            sv[n] = v;
            mx = fmaxf(mx, v);
        }
        float den = 0.f;
#pragma unroll
        for (int n = 0; n < NB_; n++) {
            sv[n] = expf(sv[n] - mx);
            den += sv[n];
        }
        float inv = 1.0f / den;
        float acc = 0.f;
#pragma unroll
        for (int n = 0; n < NB_; n++)
            acc += g_score[b * NB_ + n] * sv[n] * inv;
        out[b] = acc;
    }
}

// ---------------------------------------------------------------------------
extern "C" void kernel_launch(void* const* d_in, const int* in_sizes, int n_in,
                              void* d_out, int out_size)
{
    const float* word_atten   = (const float*)d_in[0];
    const float* hq           = (const float*)d_in[1];
    const float* can          = (const float*)d_in[2];
    const float* rep          = (const float*)d_in[3];
    const float* rep_cur      = (const float*)d_in[4];
    const float* mask_hq      = (const float*)d_in[5];
    const float* mask_can     = (const float*)d_in[6];
    const float* mask_session = (const float*)d_in[7];
    const float* W_dense      = (const float*)d_in[8];
    const float* b_dense      = (const float*)d_in[9];
    const float* W_att        = (const float*)d_in[10];
    const float* b_att        = (const float*)d_in[11];
    float* out = (float*)d_out;

    // 32768 rows (16384 hq + 16384 can), 8 rows per block
    normalize_kernel<<<4096, 256>>>(hq, can);

    dim3 grid2(NB_, B_);
    knrm_kernel<<<grid2, 256>>>(word_atten, mask_hq, mask_can, mask_session,
                                W_dense, b_dense);

    attend_kernel<<<B_, 256>>>(rep, rep_cur, mask_session, W_att, b_att, out);
}